// round 2
// baseline (speedup 1.0000x reference)
#include <cuda_runtime.h>

// Algebraic reduction of the reference:
//   The fusion loop computes tr = (op - op) * weight == 0 exactly (finite op),
//   so real_sum == 0 and the output is
//     out[b] = relu(relu(bf1) @ Wf2^T + bf2) @ Wf3^T + bf3   (same scalar, all b)
// Only bf1, Wf2, bf2, Wf3, bf3 are live.
//
// Expected input order (setup_inputs):
//   0 word_indexes 1 video 2 audio 3 embed_E 4 phase0 5 phase1 6 phase2
//   7 W_ih 8 W_hh 9 b_ih 10 b_hh 11 Wt 12 bt
//   13 Wv1 14 bv1 15 Wv2 16 bv2 17 Wv3 18 bv3
//   19 Wa1 20 ba1 21 Wa2 22 ba2 23 Wa3 24 ba3
//   25 mod_w 26 Wf1 27 bf1 28 Wf2 29 bf2 30 Wf3 31 bf3
// We anchor on Wf1's unique element count (128*32768) and take the five
// tensors after it, falling back to the hard-coded indices.

#define PF  128
#define BSZ 32

__global__ __launch_bounds__(PF, 1)
void TF2N_35347580846484_kernel(const float* __restrict__ bf1,
                                const float* __restrict__ Wf2,
                                const float* __restrict__ bf2,
                                const float* __restrict__ Wf3,
                                const float* __restrict__ bf3,
                                float* __restrict__ out) {
    __shared__ float z1[PF];
    __shared__ float red[PF / 32];

    const int i = threadIdx.x;

    // Layer 1: z1 = relu(0 @ Wf1^T + bf1) = relu(bf1)
    z1[i] = fmaxf(bf1[i], 0.0f);
    __syncthreads();

    // Layer 2: z2[i] = relu(Wf2[i,:] . z1 + bf2[i])
    float acc = bf2[i];
    const float* __restrict__ w = Wf2 + i * PF;
#pragma unroll 8
    for (int j = 0; j < PF; ++j) {
        acc = fmaf(w[j], z1[j], acc);   // z1[j] is a broadcast smem read
    }
    const float z2 = fmaxf(acc, 0.0f);

    // Layer 3 (OUT=1): s = Wf3 . z2 + bf3
    float p = Wf3[i] * z2;
#pragma unroll
    for (int o = 16; o > 0; o >>= 1)
        p += __shfl_down_sync(0xffffffffu, p, o);
    if ((i & 31) == 0) red[i >> 5] = p;
    __syncthreads();

    if (i < 32) {
        float s = (i < PF / 32) ? red[i] : 0.0f;
#pragma unroll
        for (int o = 2; o > 0; o >>= 1)
            s += __shfl_down_sync(0xffffffffu, s, o);
        s += bf3[0];
        s = __shfl_sync(0xffffffffu, s, 0);
        // Broadcast the scalar to all B=32 output rows (one STG per lane).
        out[i] = s;
    }
}

extern "C" void kernel_launch(void* const* d_in, const int* in_sizes, int n_in,
                              void* d_out, int out_size) {
    (void)out_size;

    // Defensive anchor: Wf1 has 128*32768 = 4194304 elements, unique by far.
    int wf1 = 26;
    for (int k = 0; k < n_in; ++k) {
        if (in_sizes[k] == 128 * 32768) { wf1 = k; break; }
    }

    const float* bf1 = (const float*)d_in[wf1 + 1];
    const float* Wf2 = (const float*)d_in[wf1 + 2];
    const float* bf2 = (const float*)d_in[wf1 + 3];
    const float* Wf3 = (const float*)d_in[wf1 + 4];
    const float* bf3 = (const float*)d_in[wf1 + 5];
    float* out = (float*)d_out;

    TF2N_35347580846484_kernel<<<1, PF>>>(bf1, Wf2, bf2, Wf3, bf3, out);
}

// round 3
// speedup vs baseline: 1.7879x; 1.7879x over previous
#include <cuda_runtime.h>

// Algebraic reduction of the reference (verified R2, rel_err 2.1e-7):
//   tr = (op - op) * weight == 0 exactly  =>  real_sum == 0  =>
//   out[b] = relu(relu(bf1) @ Wf2^T + bf2) @ Wf3^T + bf3   (same scalar, all b)
// Live inputs: bf1, Wf2(128x128), bf2, Wf3, bf3 — located by anchoring on
// Wf1's unique element count (128*32768) in in_sizes.
//
// R3 change: latency-bound fix. Old kernel: 128 threads, each serially walking
// a Wf2 row (uncoalesced, MLP~8) -> ~16 dependent DRAM batches -> 14us.
// New kernel: 1024 threads; 8 threads per output row; ALL of Wf2 (64KB) issued
// as 4096 concurrent LDG.128 -> one DRAM round-trip, then shuffle reduces.

#define PF 128

__global__ __launch_bounds__(1024, 1)
void TF2N_35347580846484_kernel(const float* __restrict__ bf1,
                                const float* __restrict__ Wf2,
                                const float* __restrict__ bf2,
                                const float* __restrict__ Wf3,
                                const float* __restrict__ bf3,
                                float* __restrict__ out) {
    __shared__ float4 z1v[PF / 4];     // relu(bf1) as float4
    __shared__ float  wsum[32];        // per-warp partial sums

    const int t = threadIdx.x;
    const int r = t >> 3;              // output row 0..127
    const int c = t & 7;               // 16-col chunk within the row

    // Issue ALL global loads up front so they fly concurrently.
    const float4* __restrict__ wp =
        reinterpret_cast<const float4*>(Wf2 + r * PF + c * 16);
    const float4 w0 = wp[0];
    const float4 w1 = wp[1];
    const float4 w2 = wp[2];
    const float4 w3 = wp[3];
    const float  b2 = bf2[r];          // issued early, used after reduce
    const float  w3r = Wf3[r];
    const float  b3 = bf3[0];

    if (t < PF)
        reinterpret_cast<float*>(z1v)[t] = fmaxf(bf1[t], 0.0f);
    __syncthreads();

    // 16-element partial dot: Wf2[r, c*16 .. c*16+15] . z1[c*16 .. c*16+15]
    const float4 a0 = z1v[c * 4 + 0];
    const float4 a1 = z1v[c * 4 + 1];
    const float4 a2 = z1v[c * 4 + 2];
    const float4 a3 = z1v[c * 4 + 3];

    float acc;
    acc = w0.x * a0.x;
    acc = fmaf(w0.y, a0.y, acc);
    acc = fmaf(w0.z, a0.z, acc);
    acc = fmaf(w0.w, a0.w, acc);
    acc = fmaf(w1.x, a1.x, acc);
    acc = fmaf(w1.y, a1.y, acc);
    acc = fmaf(w1.z, a1.z, acc);
    acc = fmaf(w1.w, a1.w, acc);
    acc = fmaf(w2.x, a2.x, acc);
    acc = fmaf(w2.y, a2.y, acc);
    acc = fmaf(w2.z, a2.z, acc);
    acc = fmaf(w2.w, a2.w, acc);
    acc = fmaf(w3.x, a3.x, acc);
    acc = fmaf(w3.y, a3.y, acc);
    acc = fmaf(w3.z, a3.z, acc);
    acc = fmaf(w3.w, a3.w, acc);

    // Reduce the 8 chunk-partials of this row (lanes share upper bits).
    acc += __shfl_xor_sync(0xffffffffu, acc, 1);
    acc += __shfl_xor_sync(0xffffffffu, acc, 2);
    acc += __shfl_xor_sync(0xffffffffu, acc, 4);

    // Row leader folds in bias + relu + Wf3 weight; others contribute 0.
    float contrib = (c == 0) ? fmaxf(acc + b2, 0.0f) * w3r : 0.0f;

    // Sum the 4 row-contributions of this warp (leaders at lanes 0,8,16,24).
    contrib += __shfl_xor_sync(0xffffffffu, contrib, 8);
    contrib += __shfl_xor_sync(0xffffffffu, contrib, 16);

    if ((t & 31) == 0) wsum[t >> 5] = contrib;
    __syncthreads();

    // Final 32-value reduce in warp 0; broadcast scalar to all B=32 outputs.
    if (t < 32) {
        float s = wsum[t];
#pragma unroll
        for (int o = 16; o > 0; o >>= 1)
            s += __shfl_xor_sync(0xffffffffu, s, o);
        s += b3;
        out[t] = s;
    }
}

extern "C" void kernel_launch(void* const* d_in, const int* in_sizes, int n_in,
                              void* d_out, int out_size) {
    (void)out_size;

    // Anchor: Wf1 has 128*32768 = 4194304 elements, unique by far.
    int wf1 = 26;
    for (int k = 0; k < n_in; ++k) {
        if (in_sizes[k] == 128 * 32768) { wf1 = k; break; }
    }

    const float* bf1 = (const float*)d_in[wf1 + 1];
    const float* Wf2 = (const float*)d_in[wf1 + 2];
    const float* bf2 = (const float*)d_in[wf1 + 3];
    const float* Wf3 = (const float*)d_in[wf1 + 4];
    const float* bf3 = (const float*)d_in[wf1 + 5];
    float* out = (float*)d_out;

    TF2N_35347580846484_kernel<<<1, 1024>>>(bf1, Wf2, bf2, Wf3, bf3, out);
}

// round 4
// speedup vs baseline: 2.1553x; 1.2055x over previous
#include <cuda_runtime.h>

// Algebraic reduction of the reference (verified R2/R3, rel_err ~1.4e-7):
//   tr = (op - op) * weight == 0 exactly  =>  real_sum == 0  =>
//   out[b] = relu(relu(bf1) @ Wf2^T + bf2) @ Wf3^T + bf3   (same scalar, all b)
// Live inputs: bf1, Wf2(128x128), bf2, Wf3, bf3 — located by anchoring on
// Wf1's unique element count (128*32768) in in_sizes.
//
// R4 change: remove the z1 smem staging (LDG->STS->BAR->LDS serial chain).
// Each thread redundantly loads its 16 bf1 values straight from L2 (hot,
// 512B) alongside its Wf2 chunk — one concurrent load window, zero barriers
// before the FMA chain. Only one barrier remains (cross-warp reduce).

#define PF 128

__global__ __launch_bounds__(1024, 1)
void TF2N_35347580846484_kernel(const float* __restrict__ bf1,
                                const float* __restrict__ Wf2,
                                const float* __restrict__ bf2,
                                const float* __restrict__ Wf3,
                                const float* __restrict__ bf3,
                                float* __restrict__ out) {
    __shared__ float wsum[32];         // per-warp partial sums

    const int t = threadIdx.x;
    const int r = t >> 3;              // output row 0..127
    const int c = t & 7;               // 16-col chunk within the row

    // Issue ALL global loads up front; every one is independent.
    const float4* __restrict__ wp =
        reinterpret_cast<const float4*>(Wf2 + r * PF + c * 16);
    const float4* __restrict__ zp =
        reinterpret_cast<const float4*>(bf1 + c * 16);
    const float4 w0 = wp[0];
    const float4 w1 = wp[1];
    const float4 w2 = wp[2];
    const float4 w3 = wp[3];
    float4 a0 = zp[0];
    float4 a1 = zp[1];
    float4 a2 = zp[2];
    float4 a3 = zp[3];
    const float  b2  = bf2[r];
    const float  w3r = Wf3[r];
    const float  b3  = bf3[0];

    // relu(bf1) in registers
    a0.x = fmaxf(a0.x, 0.0f); a0.y = fmaxf(a0.y, 0.0f);
    a0.z = fmaxf(a0.z, 0.0f); a0.w = fmaxf(a0.w, 0.0f);
    a1.x = fmaxf(a1.x, 0.0f); a1.y = fmaxf(a1.y, 0.0f);
    a1.z = fmaxf(a1.z, 0.0f); a1.w = fmaxf(a1.w, 0.0f);
    a2.x = fmaxf(a2.x, 0.0f); a2.y = fmaxf(a2.y, 0.0f);
    a2.z = fmaxf(a2.z, 0.0f); a2.w = fmaxf(a2.w, 0.0f);
    a3.x = fmaxf(a3.x, 0.0f); a3.y = fmaxf(a3.y, 0.0f);
    a3.z = fmaxf(a3.z, 0.0f); a3.w = fmaxf(a3.w, 0.0f);

    // 16-element partial dot: Wf2[r, c*16 .. c*16+15] . relu(bf1)[c*16..]
    float acc;
    acc = w0.x * a0.x;
    acc = fmaf(w0.y, a0.y, acc);
    acc = fmaf(w0.z, a0.z, acc);
    acc = fmaf(w0.w, a0.w, acc);
    acc = fmaf(w1.x, a1.x, acc);
    acc = fmaf(w1.y, a1.y, acc);
    acc = fmaf(w1.z, a1.z, acc);
    acc = fmaf(w1.w, a1.w, acc);
    acc = fmaf(w2.x, a2.x, acc);
    acc = fmaf(w2.y, a2.y, acc);
    acc = fmaf(w2.z, a2.z, acc);
    acc = fmaf(w2.w, a2.w, acc);
    acc = fmaf(w3.x, a3.x, acc);
    acc = fmaf(w3.y, a3.y, acc);
    acc = fmaf(w3.z, a3.z, acc);
    acc = fmaf(w3.w, a3.w, acc);

    // Reduce the 8 chunk-partials of this row.
    acc += __shfl_xor_sync(0xffffffffu, acc, 1);
    acc += __shfl_xor_sync(0xffffffffu, acc, 2);
    acc += __shfl_xor_sync(0xffffffffu, acc, 4);

    // Row leader folds in bias + relu + Wf3 weight; others contribute 0.
    float contrib = (c == 0) ? fmaxf(acc + b2, 0.0f) * w3r : 0.0f;

    // Sum the 4 row-contributions of this warp (leaders at lanes 0,8,16,24).
    contrib += __shfl_xor_sync(0xffffffffu, contrib, 8);
    contrib += __shfl_xor_sync(0xffffffffu, contrib, 16);

    if ((t & 31) == 0) wsum[t >> 5] = contrib;
    __syncthreads();

    // Final 32-value reduce in warp 0; broadcast scalar to all B=32 outputs.
    if (t < 32) {
        float s = wsum[t];
#pragma unroll
        for (int o = 16; o > 0; o >>= 1)
            s += __shfl_xor_sync(0xffffffffu, s, o);
        s += b3;
        out[t] = s;
    }
}

extern "C" void kernel_launch(void* const* d_in, const int* in_sizes, int n_in,
                              void* d_out, int out_size) {
    (void)out_size;

    // Anchor: Wf1 has 128*32768 = 4194304 elements, unique by far.
    int wf1 = 26;
    for (int k = 0; k < n_in; ++k) {
        if (in_sizes[k] == 128 * 32768) { wf1 = k; break; }
    }

    const float* bf1 = (const float*)d_in[wf1 + 1];
    const float* Wf2 = (const float*)d_in[wf1 + 2];
    const float* bf2 = (const float*)d_in[wf1 + 3];
    const float* Wf3 = (const float*)d_in[wf1 + 4];
    const float* bf3 = (const float*)d_in[wf1 + 5];
    float* out = (float*)d_out;

    TF2N_35347580846484_kernel<<<1, 1024>>>(bf1, Wf2, bf2, Wf3, bf3, out);
}